// round 14
// baseline (speedup 1.0000x reference)
#include <cuda_runtime.h>
#include <cuda_fp16.h>
#include <stdint.h>

#define D_IN   256
#define D_HID  64
#define D_EMB  32
#define MAX_NODES 100000

// Scratch (static __device__ — no allocation allowed)
__device__ __half g_Hh [MAX_NODES * D_HID];  // x @ W1            (fp16)
__device__ float  g_S1 [MAX_NODES * D_HID];  // A @ H             (fp32)
__device__ __half g_Z1h[MAX_NODES * D_EMB];  // relu(S1+b1) @ W2  (fp16)
__device__ float  g_S2 [MAX_NODES * D_EMB];  // A @ Z1            (fp32)
__device__ __half g_S2h[MAX_NODES * D_EMB];  // fp16 (S2+b2) for decoder

// ---------------------------------------------------------------------------
// TF32 helpers
// ---------------------------------------------------------------------------
__device__ __forceinline__ unsigned f2tf32(float f) {
    unsigned r;
    asm("cvt.rna.tf32.f32 %0, %1;" : "=r"(r) : "f"(f));
    return r;
}
__device__ __forceinline__ unsigned bits2tf32(unsigned b) {
    unsigned r;
    asm("cvt.rna.tf32.f32 %0, %1;" : "=r"(r) : "r"(b));
    return r;
}

__device__ __forceinline__ void mma_tf32(
    float& d0, float& d1, float& d2, float& d3,
    unsigned a0, unsigned a1, unsigned a2, unsigned a3,
    unsigned b0, unsigned b1)
{
    asm volatile(
        "mma.sync.aligned.m16n8k8.row.col.f32.tf32.tf32.f32 "
        "{%0,%1,%2,%3}, {%4,%5,%6,%7}, {%8,%9}, {%0,%1,%2,%3};"
        : "+f"(d0), "+f"(d1), "+f"(d2), "+f"(d3)
        : "r"(a0), "r"(a1), "r"(a2), "r"(a3), "r"(b0), "r"(b1));
}

__device__ __forceinline__ void cp_async16(unsigned smem_addr, const void* gptr) {
    asm volatile("cp.async.cg.shared.global [%0], [%1], 16;"
                 :: "r"(smem_addr), "l"(gptr));
}

// ---------------------------------------------------------------------------
// GEMM1 (TF32, 3-stage cp.async pipeline, fused zeroing), fp16 output
//   H = x @ W1   [n,256] @ [256,64]
// ---------------------------------------------------------------------------
#define W_STRIDE 72
#define X_STRIDE 36
#define W_WORDS  (256 * W_STRIDE)
#define X_WORDS  (128 * X_STRIDE)
#define NBUF     3
#define GEMM1_SMEM ((W_WORDS + NBUF * X_WORDS) * 4)   // 129024 bytes

__global__ __launch_bounds__(256) void gemm1_tf32_v5(
    const float* __restrict__ x, const float* __restrict__ W1, int n)
{
    extern __shared__ unsigned smem[];
    unsigned* Wsh = smem;                       // [256][72]
    float*    xsf = (float*)(smem + W_WORDS);   // [NBUF][128][36]

    int tid  = threadIdx.x;
    int warp = tid >> 5;
    int lane = tid & 31;
    int row_base = blockIdx.x * 128;
    int wm   = warp * 16;
    int qrow = lane >> 2;
    int qcol = lane & 3;

    unsigned xs_base;
    asm("{ .reg .u64 t; cvta.to.shared.u64 t, %1; cvt.u32.u64 %0, t; }"
        : "=r"(xs_base) : "l"(xsf));

    // prefetch x chunks 0 and 1 (distance-2 pipeline)
    #pragma unroll
    for (int pc = 0; pc < 2; pc++) {
        #pragma unroll
        for (int l = 0; l < 4; l++) {
            int flat = tid + l * 256;
            int r    = flat >> 3;
            int c4   = flat & 7;
            int grow = row_base + r; if (grow >= n) grow = n - 1;
            cp_async16(xs_base + (unsigned)(pc * X_WORDS + r * X_STRIDE + c4 * 4) * 4,
                       x + (size_t)grow * D_IN + pc * 32 + c4 * 4);
        }
        asm volatile("cp.async.commit_group;");
    }

    // stage whole W1 (tf32, rna)
    #pragma unroll
    for (int l = 0; l < 16; l++) {
        int flat = tid + l * 256;
        int k  = flat >> 4;
        int cc = (flat & 15) * 4;
        float4 w = __ldg((const float4*)(W1 + (size_t)k * 64 + cc));
        Wsh[k * W_STRIDE + cc + 0] = f2tf32(w.x);
        Wsh[k * W_STRIDE + cc + 1] = f2tf32(w.y);
        Wsh[k * W_STRIDE + cc + 2] = f2tf32(w.z);
        Wsh[k * W_STRIDE + cc + 3] = f2tf32(w.w);
    }

    // fused zeroing of S1 / S2 (overlaps prefetch latency)
    {
        int gtid = blockIdx.x * 256 + tid;
        int nthr = gridDim.x * 256;
        float4 z = make_float4(0.f, 0.f, 0.f, 0.f);
        for (int i = gtid; i < n * 16; i += nthr) ((float4*)g_S1)[i] = z;
        for (int i = gtid; i < n * 8;  i += nthr) ((float4*)g_S2)[i] = z;
    }

    float c[8][4];
    #pragma unroll
    for (int nt = 0; nt < 8; nt++)
        #pragma unroll
        for (int i = 0; i < 4; i++) c[nt][i] = 0.f;

    #pragma unroll
    for (int kc = 0; kc < 8; kc++) {
        // buffer kc%NBUF must be complete: allow 1 outstanding group (kc+1)
        if (kc + 1 < 8)
            asm volatile("cp.async.wait_group 1;");
        else
            asm volatile("cp.async.wait_group 0;");
        __syncthreads();

        const unsigned* xb = (const unsigned*)(xsf + (kc % NBUF) * X_WORDS);
        #pragma unroll
        for (int k8 = 0; k8 < 4; k8++) {
            int ar = wm + qrow;
            int ac = k8 * 8 + qcol;
            unsigned a0 = bits2tf32(xb[(ar    ) * X_STRIDE + ac    ]);
            unsigned a1 = bits2tf32(xb[(ar + 8) * X_STRIDE + ac    ]);
            unsigned a2 = bits2tf32(xb[(ar    ) * X_STRIDE + ac + 4]);
            unsigned a3 = bits2tf32(xb[(ar + 8) * X_STRIDE + ac + 4]);
            int kg = kc * 32 + k8 * 8 + qcol;
            #pragma unroll
            for (int nt = 0; nt < 8; nt++) {
                unsigned b0 = Wsh[(kg    ) * W_STRIDE + nt * 8 + qrow];
                unsigned b1 = Wsh[(kg + 4) * W_STRIDE + nt * 8 + qrow];
                mma_tf32(c[nt][0], c[nt][1], c[nt][2], c[nt][3],
                         a0, a1, a2, a3, b0, b1);
            }
        }
        __syncthreads();   // all reads of buffer (kc-1)%NBUF done before refill

        if (kc + 2 < 8) {
            int buf = (kc + 2) % NBUF;
            #pragma unroll
            for (int l = 0; l < 4; l++) {
                int flat = tid + l * 256;
                int r    = flat >> 3;
                int c4   = flat & 7;
                int grow = row_base + r; if (grow >= n) grow = n - 1;
                cp_async16(xs_base + (unsigned)(buf * X_WORDS + r * X_STRIDE + c4 * 4) * 4,
                           x + (size_t)grow * D_IN + (kc + 2) * 32 + c4 * 4);
            }
            asm volatile("cp.async.commit_group;");
        }
    }

    int r0 = row_base + wm + qrow;
    int cb = qcol * 2;
    #pragma unroll
    for (int nt = 0; nt < 8; nt++) {
        if (r0 < n)
            *(__half2*)(g_Hh + (size_t)r0 * D_HID + nt*8 + cb) =
                __floats2half2_rn(c[nt][0], c[nt][1]);
        if (r0 + 8 < n)
            *(__half2*)(g_Hh + (size_t)(r0 + 8) * D_HID + nt*8 + cb) =
                __floats2half2_rn(c[nt][2], c[nt][3]);
    }
}

// ---------------------------------------------------------------------------
// red.v4 helper
// ---------------------------------------------------------------------------
__device__ __forceinline__ void red_add_v4(float* p, float4 v) {
    asm volatile("red.global.add.v4.f32 [%0], {%1,%2,%3,%4};"
                 :: "l"(p), "f"(v.x), "f"(v.y), "f"(v.z), "f"(v.w)
                 : "memory");
}

// ---------------------------------------------------------------------------
// SpMM d=64: warp owns 32 edges; coalesced streaming index loads + shfl.
// ---------------------------------------------------------------------------
__global__ __launch_bounds__(256) void spmm64_kernel(
    const int* __restrict__ src, const int* __restrict__ dst,
    const float* __restrict__ val, int nnz)
{
    int lane = threadIdx.x & 31;
    long long wid = (long long)((blockIdx.x * blockDim.x + threadIdx.x) >> 5);
    long long wbase = wid * 32;
    if (wbase >= nnz) return;

    long long e = wbase + lane;
    bool ok = (e < nnz);
    long long ec = ok ? e : (nnz - 1);
    int   s = __ldcs(src + ec);
    int   d = __ldcs(dst + ec);
    float v = ok ? __ldcs(val + ec) : 0.f;

    int g = lane >> 4;          // group 0/1
    int c = lane & 15;          // channel quad

    #pragma unroll
    for (int j = 0; j < 16; j++) {
        int sl = g * 16 + j;
        int   sj = __shfl_sync(0xFFFFFFFFu, s, sl);
        int   dj = __shfl_sync(0xFFFFFFFFu, d, sl);
        float vj = __shfl_sync(0xFFFFFFFFu, v, sl);
        uint2 raw = __ldg((const uint2*)(g_Hh + (size_t)sj * D_HID) + c);
        float2 f0 = __half22float2(*(__half2*)&raw.x);
        float2 f1 = __half22float2(*(__half2*)&raw.y);
        red_add_v4(g_S1 + (size_t)dj * D_HID + c * 4,
                   make_float4(vj*f0.x, vj*f0.y, vj*f1.x, vj*f1.y));
    }
}

// ---------------------------------------------------------------------------
// GEMM2 (TF32 MMA): Z1 = relu(S1 + b1) @ W2   [n,64] @ [64,32], fp16 out.
// ---------------------------------------------------------------------------
#define Z_STRIDE 68
#define V_STRIDE 40

__global__ __launch_bounds__(256) void gemm2_mma_kernel(
    const float* __restrict__ b1, const float* __restrict__ W2, int n)
{
    __shared__ float    zs[128 * Z_STRIDE];
    __shared__ unsigned ws[64 * V_STRIDE];
    __shared__ float    b1s[64];

    int tid  = threadIdx.x;
    int warp = tid >> 5;
    int lane = tid & 31;
    int row_base = blockIdx.x * 128;
    int wm   = warp * 16;
    int qrow = lane >> 2;
    int qcol = lane & 3;

    unsigned zs_base;
    asm("{ .reg .u64 t; cvta.to.shared.u64 t, %1; cvt.u32.u64 %0, t; }"
        : "=r"(zs_base) : "l"(zs));

    #pragma unroll
    for (int l = 0; l < 8; l++) {
        int flat = tid + l * 256;
        int r  = flat >> 4;
        int c4 = flat & 15;
        int grow = row_base + r; if (grow >= n) grow = n - 1;
        cp_async16(zs_base + (unsigned)(r * Z_STRIDE + c4 * 4) * 4,
                   g_S1 + (size_t)grow * D_HID + c4 * 4);
    }
    asm volatile("cp.async.commit_group;");

    #pragma unroll
    for (int l = 0; l < 2; l++) {
        int flat = tid + l * 256;
        int k  = flat >> 3;
        int cc = (flat & 7) * 4;
        float4 w = __ldg((const float4*)(W2 + (size_t)k * 32 + cc));
        ws[k * V_STRIDE + cc + 0] = f2tf32(w.x);
        ws[k * V_STRIDE + cc + 1] = f2tf32(w.y);
        ws[k * V_STRIDE + cc + 2] = f2tf32(w.z);
        ws[k * V_STRIDE + cc + 3] = f2tf32(w.w);
    }
    if (tid < 64) b1s[tid] = __ldg(b1 + tid);

    asm volatile("cp.async.wait_group 0;");
    __syncthreads();

    float c[4][4];
    #pragma unroll
    for (int nt = 0; nt < 4; nt++)
        #pragma unroll
        for (int i = 0; i < 4; i++) c[nt][i] = 0.f;

    int ar = wm + qrow;
    #pragma unroll
    for (int k8 = 0; k8 < 8; k8++) {
        int k0 = k8 * 8 + qcol;
        float bz0 = b1s[k0];
        float bz1 = b1s[k0 + 4];
        unsigned a0 = f2tf32(fmaxf(zs[(ar    ) * Z_STRIDE + k0    ] + bz0, 0.f));
        unsigned a1 = f2tf32(fmaxf(zs[(ar + 8) * Z_STRIDE + k0    ] + bz0, 0.f));
        unsigned a2 = f2tf32(fmaxf(zs[(ar    ) * Z_STRIDE + k0 + 4] + bz1, 0.f));
        unsigned a3 = f2tf32(fmaxf(zs[(ar + 8) * Z_STRIDE + k0 + 4] + bz1, 0.f));
        #pragma unroll
        for (int nt = 0; nt < 4; nt++) {
            unsigned b0 = ws[(k0    ) * V_STRIDE + nt * 8 + qrow];
            unsigned b1v= ws[(k0 + 4) * V_STRIDE + nt * 8 + qrow];
            mma_tf32(c[nt][0], c[nt][1], c[nt][2], c[nt][3],
                     a0, a1, a2, a3, b0, b1v);
        }
    }

    int r0 = row_base + wm + qrow;
    int cb = qcol * 2;
    #pragma unroll
    for (int nt = 0; nt < 4; nt++) {
        if (r0 < n)
            *(__half2*)(g_Z1h + (size_t)r0 * D_EMB + nt*8 + cb) =
                __floats2half2_rn(c[nt][0], c[nt][1]);
        if (r0 + 8 < n)
            *(__half2*)(g_Z1h + (size_t)(r0 + 8) * D_EMB + nt*8 + cb) =
                __floats2half2_rn(c[nt][2], c[nt][3]);
    }
}

// ---------------------------------------------------------------------------
// SpMM d=32: warp owns 32 edges; coalesced streaming index loads + shfl.
// ---------------------------------------------------------------------------
__global__ __launch_bounds__(256) void spmm32_kernel(
    const int* __restrict__ src, const int* __restrict__ dst,
    const float* __restrict__ val, int nnz)
{
    int lane = threadIdx.x & 31;
    long long wid = (long long)((blockIdx.x * blockDim.x + threadIdx.x) >> 5);
    long long wbase = wid * 32;
    if (wbase >= nnz) return;

    long long e = wbase + lane;
    bool ok = (e < nnz);
    long long ec = ok ? e : (nnz - 1);
    int   s = __ldcs(src + ec);
    int   d = __ldcs(dst + ec);
    float v = ok ? __ldcs(val + ec) : 0.f;

    int g = lane >> 3;          // group 0..3
    int c = lane & 7;

    #pragma unroll
    for (int j = 0; j < 8; j++) {
        int sl = g * 8 + j;
        int   sj = __shfl_sync(0xFFFFFFFFu, s, sl);
        int   dj = __shfl_sync(0xFFFFFFFFu, d, sl);
        float vj = __shfl_sync(0xFFFFFFFFu, v, sl);
        uint2 raw = __ldg((const uint2*)(g_Z1h + (size_t)sj * D_EMB) + c);
        float2 f0 = __half22float2(*(__half2*)&raw.x);
        float2 f1 = __half22float2(*(__half2*)&raw.y);
        red_add_v4(g_S2 + (size_t)dj * D_EMB + c * 4,
                   make_float4(vj*f0.x, vj*f0.y, vj*f1.x, vj*f1.y));
    }
}

// ---------------------------------------------------------------------------
// S2 fp32 -> fp16 with fused +b2.
// ---------------------------------------------------------------------------
__global__ __launch_bounds__(256) void s2half_kernel(
    const float* __restrict__ b2, int n4)
{
    int i = blockIdx.x * blockDim.x + threadIdx.x;
    if (i >= n4) return;
    float4 bb = __ldg((const float4*)b2 + (i & 7));
    float4 v = ((const float4*)g_S2)[i];
    ((__half2*)g_S2h)[i*2    ] = __floats2half2_rn(v.x + bb.x, v.y + bb.y);
    ((__half2*)g_S2h)[i*2 + 1] = __floats2half2_rn(v.z + bb.z, v.w + bb.w);
}

// ---------------------------------------------------------------------------
// Decoder: warp owns 32 edges; coalesced index loads + shfl distribution.
// ---------------------------------------------------------------------------
__global__ __launch_bounds__(256) void decoder_kernel(
    const int* __restrict__ edge_index, float* __restrict__ out, int ne)
{
    int lane = threadIdx.x & 31;
    long long wid = (long long)((blockIdx.x * blockDim.x + threadIdx.x) >> 5);
    long long wbase = wid * 32;
    if (wbase >= ne) return;

    long long e = wbase + lane;
    bool ok = (e < ne);
    long long ec = ok ? e : (ne - 1);
    int s = __ldcs(edge_index + ec);
    int d = __ldcs(edge_index + ne + ec);

    int g = lane >> 3;
    int c = lane & 7;

    float p[8];
    #pragma unroll
    for (int j = 0; j < 8; j++) {
        int sl = g * 8 + j;
        int sj = __shfl_sync(0xFFFFFFFFu, s, sl);
        int dj = __shfl_sync(0xFFFFFFFFu, d, sl);
        uint2 ra = __ldg((const uint2*)(g_S2h + (size_t)sj * D_EMB) + c);
        uint2 rb = __ldg((const uint2*)(g_S2h + (size_t)dj * D_EMB) + c);
        float2 al = __half22float2(*(__half2*)&ra.x);
        float2 ah = __half22float2(*(__half2*)&ra.y);
        float2 bl = __half22float2(*(__half2*)&rb.x);
        float2 bh = __half22float2(*(__half2*)&rb.y);
        p[j] = al.x*bl.x + al.y*bl.y + ah.x*bh.x + ah.y*bh.y;
    }

    #pragma unroll
    for (int m = 1; m < 8; m <<= 1) {
        #pragma unroll
        for (int j = 0; j < 8; j++)
            p[j] += __shfl_xor_sync(0xFFFFFFFFu, p[j], m);
    }

    long long eo = wbase + g * 8 + c;
    if (eo < ne) out[eo] = p[c];
}

// ---------------------------------------------------------------------------
extern "C" void kernel_launch(void* const* d_in, const int* in_sizes, int n_in,
                              void* d_out, int out_size)
{
    const float* x         = (const float*)d_in[0];
    const int*   adj_src   = (const int*)  d_in[1];
    const int*   adj_dst   = (const int*)  d_in[2];
    const float* adj_val   = (const float*)d_in[3];
    const int*   edge_idx  = (const int*)  d_in[4];
    const float* W1        = (const float*)d_in[5];
    const float* b1        = (const float*)d_in[6];
    const float* W2        = (const float*)d_in[7];
    const float* b2        = (const float*)d_in[8];
    float*       out       = (float*)d_out;

    int n   = in_sizes[0] / D_IN;
    int nnz = in_sizes[3];
    int ne  = in_sizes[4] / 2;
    (void)n_in; (void)out_size;

    // GEMM1 (TF32, 3-stage cp.async, fused S1/S2 zeroing, fp16 H)
    cudaFuncSetAttribute(gemm1_tf32_v5,
                         cudaFuncAttributeMaxDynamicSharedMemorySize, GEMM1_SMEM);
    gemm1_tf32_v5<<<(n + 127) / 128, 256, GEMM1_SMEM>>>(x, W1, n);

    // SpMM1 (d=64): 1 warp per 32 edges
    {
        long long warps = ((long long)nnz + 31) / 32;
        long long total = warps * 32;
        int blocks = (int)((total + 255) / 256);
        spmm64_kernel<<<blocks, 256>>>(adj_src, adj_dst, adj_val, nnz);
    }
    // GEMM2 (TF32 MMA, fused relu + b1, fp16 Z1)
    gemm2_mma_kernel<<<(n + 127) / 128, 256>>>(b1, W2, n);
    // SpMM2 (d=32): 1 warp per 32 edges
    {
        long long warps = ((long long)nnz + 31) / 32;
        long long total = warps * 32;
        int blocks = (int)((total + 255) / 256);
        spmm32_kernel<<<blocks, 256>>>(adj_src, adj_dst, adj_val, nnz);
    }
    // S2 -> fp16 with +b2 folded
    {
        int n4 = n * 8;
        s2half_kernel<<<(n4 + 255) / 256, 256>>>(b2, n4);
    }
    // Decoder: 1 warp per 32 edges
    {
        long long warps = ((long long)ne + 31) / 32;
        long long total = warps * 32;
        int blocks = (int)((total + 255) / 256);
        decoder_kernel<<<blocks, 256>>>(edge_idx, out, ne);
    }
}

// round 15
// speedup vs baseline: 1.0419x; 1.0419x over previous
#include <cuda_runtime.h>
#include <cuda_fp16.h>
#include <stdint.h>

#define D_IN   256
#define D_HID  64
#define D_EMB  32
#define MAX_NODES 100000

// Scratch (static __device__ — no allocation allowed)
__device__ __half g_Hh [MAX_NODES * D_HID];  // x @ W1            (fp16)
__device__ float  g_S1 [MAX_NODES * D_HID];  // A @ H             (fp32)
__device__ __half g_Z1h[MAX_NODES * D_EMB];  // relu(S1+b1) @ W2  (fp16)
__device__ float  g_S2 [MAX_NODES * D_EMB];  // A @ Z1            (fp32)
__device__ __half g_S2h[MAX_NODES * D_EMB];  // fp16 (S2+b2) for decoder

// ---------------------------------------------------------------------------
// TF32 helpers
// ---------------------------------------------------------------------------
__device__ __forceinline__ unsigned f2tf32(float f) {
    unsigned r;
    asm("cvt.rna.tf32.f32 %0, %1;" : "=r"(r) : "f"(f));
    return r;
}
__device__ __forceinline__ unsigned bits2tf32(unsigned b) {
    unsigned r;
    asm("cvt.rna.tf32.f32 %0, %1;" : "=r"(r) : "r"(b));
    return r;
}

__device__ __forceinline__ void mma_tf32(
    float& d0, float& d1, float& d2, float& d3,
    unsigned a0, unsigned a1, unsigned a2, unsigned a3,
    unsigned b0, unsigned b1)
{
    asm volatile(
        "mma.sync.aligned.m16n8k8.row.col.f32.tf32.tf32.f32 "
        "{%0,%1,%2,%3}, {%4,%5,%6,%7}, {%8,%9}, {%0,%1,%2,%3};"
        : "+f"(d0), "+f"(d1), "+f"(d2), "+f"(d3)
        : "r"(a0), "r"(a1), "r"(a2), "r"(a3), "r"(b0), "r"(b1));
}

__device__ __forceinline__ void cp_async16(unsigned smem_addr, const void* gptr) {
    asm volatile("cp.async.cg.shared.global [%0], [%1], 16;"
                 :: "r"(smem_addr), "l"(gptr));
}

// ---------------------------------------------------------------------------
// GEMM1 (TF32, 4-buffer depth-3 cp.async pipeline, fp16 W staging,
//        fused zeroing), fp16 output.   H = x @ W1  [n,256] @ [256,64]
// SMEM: W1 fp16 [256][72] (36.9KB) + x fp32 [4][128][36] (73.7KB) = 110.6KB
//       -> 2 blocks/SM (same as proven v4 footprint) with 3 chunks in flight.
// ---------------------------------------------------------------------------
#define W_STRIDE 72
#define X_STRIDE 36
#define WH_HALVES (256 * W_STRIDE)            // fp16 elements
#define WH_WORDS  (WH_HALVES / 2)             // 9216 u32 words
#define X_WORDS   (128 * X_STRIDE)            // 4608 per buffer
#define NBUF      4
#define GEMM1_SMEM ((WH_WORDS + NBUF * X_WORDS) * 4)   // 110592 bytes

__global__ __launch_bounds__(256) void gemm1_tf32_v6(
    const float* __restrict__ x, const float* __restrict__ W1, int n)
{
    extern __shared__ unsigned smem[];
    __half* Wsh = (__half*)smem;                    // [256][72] fp16
    float*  xsf = (float*)(smem + WH_WORDS);        // [NBUF][128][36]

    int tid  = threadIdx.x;
    int warp = tid >> 5;
    int lane = tid & 31;
    int row_base = blockIdx.x * 128;
    int wm   = warp * 16;
    int qrow = lane >> 2;
    int qcol = lane & 3;

    unsigned xs_base;
    asm("{ .reg .u64 t; cvta.to.shared.u64 t, %1; cvt.u32.u64 %0, t; }"
        : "=r"(xs_base) : "l"(xsf));

    // prefetch x chunks 0,1,2 (distance-3 pipeline)
    #pragma unroll
    for (int pc = 0; pc < 3; pc++) {
        #pragma unroll
        for (int l = 0; l < 4; l++) {
            int flat = tid + l * 256;
            int r    = flat >> 3;
            int c4   = flat & 7;
            int grow = row_base + r; if (grow >= n) grow = n - 1;
            cp_async16(xs_base + (unsigned)(pc * X_WORDS + r * X_STRIDE + c4 * 4) * 4,
                       x + (size_t)grow * D_IN + pc * 32 + c4 * 4);
        }
        asm volatile("cp.async.commit_group;");
    }

    // stage whole W1 as fp16 (same 10-bit mantissa as tf32 — lossless here)
    #pragma unroll
    for (int l = 0; l < 16; l++) {
        int flat = tid + l * 256;
        int k  = flat >> 4;
        int cc = (flat & 15) * 4;
        float4 w = __ldg((const float4*)(W1 + (size_t)k * 64 + cc));
        __half2* p = (__half2*)&Wsh[k * W_STRIDE + cc];
        p[0] = __floats2half2_rn(w.x, w.y);
        p[1] = __floats2half2_rn(w.z, w.w);
    }

    // fused zeroing of S1 / S2 (overlaps prefetch latency)
    {
        int gtid = blockIdx.x * 256 + tid;
        int nthr = gridDim.x * 256;
        float4 z = make_float4(0.f, 0.f, 0.f, 0.f);
        for (int i = gtid; i < n * 16; i += nthr) ((float4*)g_S1)[i] = z;
        for (int i = gtid; i < n * 8;  i += nthr) ((float4*)g_S2)[i] = z;
    }

    float c[8][4];
    #pragma unroll
    for (int nt = 0; nt < 8; nt++)
        #pragma unroll
        for (int i = 0; i < 4; i++) c[nt][i] = 0.f;

    #pragma unroll
    for (int kc = 0; kc < 8; kc++) {
        // ensure group kc complete; up to 2 newer groups may stay in flight
        if (kc + 2 < 8)
            asm volatile("cp.async.wait_group 2;");
        else if (kc + 1 < 8)
            asm volatile("cp.async.wait_group 1;");
        else
            asm volatile("cp.async.wait_group 0;");
        __syncthreads();

        const unsigned* xb = (const unsigned*)(xsf + (kc % NBUF) * X_WORDS);
        #pragma unroll
        for (int k8 = 0; k8 < 4; k8++) {
            int ar = wm + qrow;
            int ac = k8 * 8 + qcol;
            unsigned a0 = bits2tf32(xb[(ar    ) * X_STRIDE + ac    ]);
            unsigned a1 = bits2tf32(xb[(ar + 8) * X_STRIDE + ac    ]);
            unsigned a2 = bits2tf32(xb[(ar    ) * X_STRIDE + ac + 4]);
            unsigned a3 = bits2tf32(xb[(ar + 8) * X_STRIDE + ac + 4]);
            int kg = kc * 32 + k8 * 8 + qcol;
            #pragma unroll
            for (int nt = 0; nt < 8; nt++) {
                unsigned b0 = __float_as_uint(
                    __half2float(Wsh[(kg    ) * W_STRIDE + nt * 8 + qrow]));
                unsigned b1 = __float_as_uint(
                    __half2float(Wsh[(kg + 4) * W_STRIDE + nt * 8 + qrow]));
                mma_tf32(c[nt][0], c[nt][1], c[nt][2], c[nt][3],
                         a0, a1, a2, a3, b0, b1);
            }
        }
        __syncthreads();   // reads of buffer (kc+3)%NBUF's old contents done

        if (kc + 3 < 8) {
            int buf = (kc + 3) % NBUF;
            #pragma unroll
            for (int l = 0; l < 4; l++) {
                int flat = tid + l * 256;
                int r    = flat >> 3;
                int c4   = flat & 7;
                int grow = row_base + r; if (grow >= n) grow = n - 1;
                cp_async16(xs_base + (unsigned)(buf * X_WORDS + r * X_STRIDE + c4 * 4) * 4,
                           x + (size_t)grow * D_IN + (kc + 3) * 32 + c4 * 4);
            }
            asm volatile("cp.async.commit_group;");
        }
    }

    int r0 = row_base + wm + qrow;
    int cb = qcol * 2;
    #pragma unroll
    for (int nt = 0; nt < 8; nt++) {
        if (r0 < n)
            *(__half2*)(g_Hh + (size_t)r0 * D_HID + nt*8 + cb) =
                __floats2half2_rn(c[nt][0], c[nt][1]);
        if (r0 + 8 < n)
            *(__half2*)(g_Hh + (size_t)(r0 + 8) * D_HID + nt*8 + cb) =
                __floats2half2_rn(c[nt][2], c[nt][3]);
    }
}

// ---------------------------------------------------------------------------
// red.v4 helper
// ---------------------------------------------------------------------------
__device__ __forceinline__ void red_add_v4(float* p, float4 v) {
    asm volatile("red.global.add.v4.f32 [%0], {%1,%2,%3,%4};"
                 :: "l"(p), "f"(v.x), "f"(v.y), "f"(v.z), "f"(v.w)
                 : "memory");
}

// ---------------------------------------------------------------------------
// SpMM d=64: warp owns 32 edges; coalesced streaming index loads + shfl.
// ---------------------------------------------------------------------------
__global__ __launch_bounds__(256) void spmm64_kernel(
    const int* __restrict__ src, const int* __restrict__ dst,
    const float* __restrict__ val, int nnz)
{
    int lane = threadIdx.x & 31;
    long long wid = (long long)((blockIdx.x * blockDim.x + threadIdx.x) >> 5);
    long long wbase = wid * 32;
    if (wbase >= nnz) return;

    long long e = wbase + lane;
    bool ok = (e < nnz);
    long long ec = ok ? e : (nnz - 1);
    int   s = __ldcs(src + ec);
    int   d = __ldcs(dst + ec);
    float v = ok ? __ldcs(val + ec) : 0.f;

    int g = lane >> 4;          // group 0/1
    int c = lane & 15;          // channel quad

    #pragma unroll
    for (int j = 0; j < 16; j++) {
        int sl = g * 16 + j;
        int   sj = __shfl_sync(0xFFFFFFFFu, s, sl);
        int   dj = __shfl_sync(0xFFFFFFFFu, d, sl);
        float vj = __shfl_sync(0xFFFFFFFFu, v, sl);
        uint2 raw = __ldg((const uint2*)(g_Hh + (size_t)sj * D_HID) + c);
        float2 f0 = __half22float2(*(__half2*)&raw.x);
        float2 f1 = __half22float2(*(__half2*)&raw.y);
        red_add_v4(g_S1 + (size_t)dj * D_HID + c * 4,
                   make_float4(vj*f0.x, vj*f0.y, vj*f1.x, vj*f1.y));
    }
}

// ---------------------------------------------------------------------------
// GEMM2 (TF32 MMA): Z1 = relu(S1 + b1) @ W2   [n,64] @ [64,32], fp16 out.
// ---------------------------------------------------------------------------
#define Z_STRIDE 68
#define V_STRIDE 40

__global__ __launch_bounds__(256) void gemm2_mma_kernel(
    const float* __restrict__ b1, const float* __restrict__ W2, int n)
{
    __shared__ float    zs[128 * Z_STRIDE];
    __shared__ unsigned ws[64 * V_STRIDE];
    __shared__ float    b1s[64];

    int tid  = threadIdx.x;
    int warp = tid >> 5;
    int lane = tid & 31;
    int row_base = blockIdx.x * 128;
    int wm   = warp * 16;
    int qrow = lane >> 2;
    int qcol = lane & 3;

    unsigned zs_base;
    asm("{ .reg .u64 t; cvta.to.shared.u64 t, %1; cvt.u32.u64 %0, t; }"
        : "=r"(zs_base) : "l"(zs));

    #pragma unroll
    for (int l = 0; l < 8; l++) {
        int flat = tid + l * 256;
        int r  = flat >> 4;
        int c4 = flat & 15;
        int grow = row_base + r; if (grow >= n) grow = n - 1;
        cp_async16(zs_base + (unsigned)(r * Z_STRIDE + c4 * 4) * 4,
                   g_S1 + (size_t)grow * D_HID + c4 * 4);
    }
    asm volatile("cp.async.commit_group;");

    #pragma unroll
    for (int l = 0; l < 2; l++) {
        int flat = tid + l * 256;
        int k  = flat >> 3;
        int cc = (flat & 7) * 4;
        float4 w = __ldg((const float4*)(W2 + (size_t)k * 32 + cc));
        ws[k * V_STRIDE + cc + 0] = f2tf32(w.x);
        ws[k * V_STRIDE + cc + 1] = f2tf32(w.y);
        ws[k * V_STRIDE + cc + 2] = f2tf32(w.z);
        ws[k * V_STRIDE + cc + 3] = f2tf32(w.w);
    }
    if (tid < 64) b1s[tid] = __ldg(b1 + tid);

    asm volatile("cp.async.wait_group 0;");
    __syncthreads();

    float c[4][4];
    #pragma unroll
    for (int nt = 0; nt < 4; nt++)
        #pragma unroll
        for (int i = 0; i < 4; i++) c[nt][i] = 0.f;

    int ar = wm + qrow;
    #pragma unroll
    for (int k8 = 0; k8 < 8; k8++) {
        int k0 = k8 * 8 + qcol;
        float bz0 = b1s[k0];
        float bz1 = b1s[k0 + 4];
        unsigned a0 = f2tf32(fmaxf(zs[(ar    ) * Z_STRIDE + k0    ] + bz0, 0.f));
        unsigned a1 = f2tf32(fmaxf(zs[(ar + 8) * Z_STRIDE + k0    ] + bz0, 0.f));
        unsigned a2 = f2tf32(fmaxf(zs[(ar    ) * Z_STRIDE + k0 + 4] + bz1, 0.f));
        unsigned a3 = f2tf32(fmaxf(zs[(ar + 8) * Z_STRIDE + k0 + 4] + bz1, 0.f));
        #pragma unroll
        for (int nt = 0; nt < 4; nt++) {
            unsigned b0 = ws[(k0    ) * V_STRIDE + nt * 8 + qrow];
            unsigned b1v= ws[(k0 + 4) * V_STRIDE + nt * 8 + qrow];
            mma_tf32(c[nt][0], c[nt][1], c[nt][2], c[nt][3],
                     a0, a1, a2, a3, b0, b1v);
        }
    }

    int r0 = row_base + wm + qrow;
    int cb = qcol * 2;
    #pragma unroll
    for (int nt = 0; nt < 4; nt++) {
        if (r0 < n)
            *(__half2*)(g_Z1h + (size_t)r0 * D_EMB + nt*8 + cb) =
                __floats2half2_rn(c[nt][0], c[nt][1]);
        if (r0 + 8 < n)
            *(__half2*)(g_Z1h + (size_t)(r0 + 8) * D_EMB + nt*8 + cb) =
                __floats2half2_rn(c[nt][2], c[nt][3]);
    }
}

// ---------------------------------------------------------------------------
// SpMM d=32: warp owns 32 edges; coalesced streaming index loads + shfl.
// ---------------------------------------------------------------------------
__global__ __launch_bounds__(256) void spmm32_kernel(
    const int* __restrict__ src, const int* __restrict__ dst,
    const float* __restrict__ val, int nnz)
{
    int lane = threadIdx.x & 31;
    long long wid = (long long)((blockIdx.x * blockDim.x + threadIdx.x) >> 5);
    long long wbase = wid * 32;
    if (wbase >= nnz) return;

    long long e = wbase + lane;
    bool ok = (e < nnz);
    long long ec = ok ? e : (nnz - 1);
    int   s = __ldcs(src + ec);
    int   d = __ldcs(dst + ec);
    float v = ok ? __ldcs(val + ec) : 0.f;

    int g = lane >> 3;          // group 0..3
    int c = lane & 7;

    #pragma unroll
    for (int j = 0; j < 8; j++) {
        int sl = g * 8 + j;
        int   sj = __shfl_sync(0xFFFFFFFFu, s, sl);
        int   dj = __shfl_sync(0xFFFFFFFFu, d, sl);
        float vj = __shfl_sync(0xFFFFFFFFu, v, sl);
        uint2 raw = __ldg((const uint2*)(g_Z1h + (size_t)sj * D_EMB) + c);
        float2 f0 = __half22float2(*(__half2*)&raw.x);
        float2 f1 = __half22float2(*(__half2*)&raw.y);
        red_add_v4(g_S2 + (size_t)dj * D_EMB + c * 4,
                   make_float4(vj*f0.x, vj*f0.y, vj*f1.x, vj*f1.y));
    }
}

// ---------------------------------------------------------------------------
// S2 fp32 -> fp16 with fused +b2.
// ---------------------------------------------------------------------------
__global__ __launch_bounds__(256) void s2half_kernel(
    const float* __restrict__ b2, int n4)
{
    int i = blockIdx.x * blockDim.x + threadIdx.x;
    if (i >= n4) return;
    float4 bb = __ldg((const float4*)b2 + (i & 7));
    float4 v = ((const float4*)g_S2)[i];
    ((__half2*)g_S2h)[i*2    ] = __floats2half2_rn(v.x + bb.x, v.y + bb.y);
    ((__half2*)g_S2h)[i*2 + 1] = __floats2half2_rn(v.z + bb.z, v.w + bb.w);
}

// ---------------------------------------------------------------------------
// Decoder: warp owns 32 edges; coalesced index loads + shfl distribution.
// ---------------------------------------------------------------------------
__global__ __launch_bounds__(256) void decoder_kernel(
    const int* __restrict__ edge_index, float* __restrict__ out, int ne)
{
    int lane = threadIdx.x & 31;
    long long wid = (long long)((blockIdx.x * blockDim.x + threadIdx.x) >> 5);
    long long wbase = wid * 32;
    if (wbase >= ne) return;

    long long e = wbase + lane;
    bool ok = (e < ne);
    long long ec = ok ? e : (ne - 1);
    int s = __ldcs(edge_index + ec);
    int d = __ldcs(edge_index + ne + ec);

    int g = lane >> 3;
    int c = lane & 7;

    float p[8];
    #pragma unroll
    for (int j = 0; j < 8; j++) {
        int sl = g * 8 + j;
        int sj = __shfl_sync(0xFFFFFFFFu, s, sl);
        int dj = __shfl_sync(0xFFFFFFFFu, d, sl);
        uint2 ra = __ldg((const uint2*)(g_S2h + (size_t)sj * D_EMB) + c);
        uint2 rb = __ldg((const uint2*)(g_S2h + (size_t)dj * D_EMB) + c);
        float2 al = __half22float2(*(__half2*)&ra.x);
        float2 ah = __half22float2(*(__half2*)&ra.y);
        float2 bl = __half22float2(*(__half2*)&rb.x);
        float2 bh = __half22float2(*(__half2*)&rb.y);
        p[j] = al.x*bl.x + al.y*bl.y + ah.x*bh.x + ah.y*bh.y;
    }

    #pragma unroll
    for (int m = 1; m < 8; m <<= 1) {
        #pragma unroll
        for (int j = 0; j < 8; j++)
            p[j] += __shfl_xor_sync(0xFFFFFFFFu, p[j], m);
    }

    long long eo = wbase + g * 8 + c;
    if (eo < ne) out[eo] = p[c];
}

// ---------------------------------------------------------------------------
extern "C" void kernel_launch(void* const* d_in, const int* in_sizes, int n_in,
                              void* d_out, int out_size)
{
    const float* x         = (const float*)d_in[0];
    const int*   adj_src   = (const int*)  d_in[1];
    const int*   adj_dst   = (const int*)  d_in[2];
    const float* adj_val   = (const float*)d_in[3];
    const int*   edge_idx  = (const int*)  d_in[4];
    const float* W1        = (const float*)d_in[5];
    const float* b1        = (const float*)d_in[6];
    const float* W2        = (const float*)d_in[7];
    const float* b2        = (const float*)d_in[8];
    float*       out       = (float*)d_out;

    int n   = in_sizes[0] / D_IN;
    int nnz = in_sizes[3];
    int ne  = in_sizes[4] / 2;
    (void)n_in; (void)out_size;

    // GEMM1 (TF32, depth-3 cp.async, fp16 W staging, fused zeroing)
    cudaFuncSetAttribute(gemm1_tf32_v6,
                         cudaFuncAttributeMaxDynamicSharedMemorySize, GEMM1_SMEM);
    gemm1_tf32_v6<<<(n + 127) / 128, 256, GEMM1_SMEM>>>(x, W1, n);

    // SpMM1 (d=64): 1 warp per 32 edges
    {
        long long warps = ((long long)nnz + 31) / 32;
        long long total = warps * 32;
        int blocks = (int)((total + 255) / 256);
        spmm64_kernel<<<blocks, 256>>>(adj_src, adj_dst, adj_val, nnz);
    }
    // GEMM2 (TF32 MMA, fused relu + b1, fp16 Z1)
    gemm2_mma_kernel<<<(n + 127) / 128, 256>>>(b1, W2, n);
    // SpMM2 (d=32): 1 warp per 32 edges
    {
        long long warps = ((long long)nnz + 31) / 32;
        long long total = warps * 32;
        int blocks = (int)((total + 255) / 256);
        spmm32_kernel<<<blocks, 256>>>(adj_src, adj_dst, adj_val, nnz);
    }
    // S2 -> fp16 with +b2 folded
    {
        int n4 = n * 8;
        s2half_kernel<<<(n4 + 255) / 256, 256>>>(b2, n4);
    }
    // Decoder: 1 warp per 32 edges
    {
        long long warps = ((long long)ne + 31) / 32;
        long long total = warps * 32;
        int blocks = (int)((total + 255) / 256);
        decoder_kernel<<<blocks, 256>>>(edge_idx, out, ne);
    }
}

// round 16
// speedup vs baseline: 1.0481x; 1.0060x over previous
#include <cuda_runtime.h>
#include <cuda_fp16.h>
#include <stdint.h>

#define D_IN   256
#define D_HID  64
#define D_EMB  32
#define MAX_NODES 100000

// Scratch (static __device__ — no allocation allowed)
__device__ __half g_Hh [MAX_NODES * D_HID];  // x @ W1            (fp16)
__device__ float  g_S1 [MAX_NODES * D_HID];  // A @ H             (fp32)
__device__ __half g_Z1h[MAX_NODES * D_EMB];  // relu(S1+b1) @ W2  (fp16)
__device__ float  g_S2 [MAX_NODES * D_EMB];  // A @ Z1            (fp32)
__device__ __half g_S2h[MAX_NODES * D_EMB];  // fp16 (S2+b2) for decoder

// ---------------------------------------------------------------------------
// TF32 helpers
// ---------------------------------------------------------------------------
__device__ __forceinline__ unsigned f2tf32(float f) {
    unsigned r;
    asm("cvt.rna.tf32.f32 %0, %1;" : "=r"(r) : "f"(f));
    return r;
}
__device__ __forceinline__ unsigned bits2tf32(unsigned b) {
    unsigned r;
    asm("cvt.rna.tf32.f32 %0, %1;" : "=r"(r) : "r"(b));
    return r;
}

__device__ __forceinline__ void mma_tf32(
    float& d0, float& d1, float& d2, float& d3,
    unsigned a0, unsigned a1, unsigned a2, unsigned a3,
    unsigned b0, unsigned b1)
{
    asm volatile(
        "mma.sync.aligned.m16n8k8.row.col.f32.tf32.tf32.f32 "
        "{%0,%1,%2,%3}, {%4,%5,%6,%7}, {%8,%9}, {%0,%1,%2,%3};"
        : "+f"(d0), "+f"(d1), "+f"(d2), "+f"(d3)
        : "r"(a0), "r"(a1), "r"(a2), "r"(a3), "r"(b0), "r"(b1));
}

__device__ __forceinline__ void cp_async16(unsigned smem_addr, const void* gptr) {
    asm volatile("cp.async.cg.shared.global [%0], [%1], 16;"
                 :: "r"(smem_addr), "l"(gptr));
}

// ---------------------------------------------------------------------------
// GEMM1 (TF32 + cp.async double buffer + fused zeroing), fp16 output
//   H = x @ W1   [n,256] @ [256,64]          (proven R13 configuration)
// ---------------------------------------------------------------------------
#define W_STRIDE 72
#define X_STRIDE 36
#define W_WORDS  (256 * W_STRIDE)
#define X_WORDS  (128 * X_STRIDE)
#define GEMM1_SMEM ((W_WORDS + 2 * X_WORDS) * 4)

__global__ __launch_bounds__(256) void gemm1_tf32_v4(
    const float* __restrict__ x, const float* __restrict__ W1, int n)
{
    extern __shared__ unsigned smem[];
    unsigned* Wsh = smem;                       // [256][72]
    float*    xsf = (float*)(smem + W_WORDS);   // [2][128][36]

    int tid  = threadIdx.x;
    int warp = tid >> 5;
    int lane = tid & 31;
    int row_base = blockIdx.x * 128;
    int wm   = warp * 16;
    int qrow = lane >> 2;
    int qcol = lane & 3;

    unsigned xs_base;
    asm("{ .reg .u64 t; cvta.to.shared.u64 t, %1; cvt.u32.u64 %0, t; }"
        : "=r"(xs_base) : "l"(xsf));

    #pragma unroll
    for (int l = 0; l < 4; l++) {
        int flat = tid + l * 256;
        int r    = flat >> 3;
        int c4   = flat & 7;
        int grow = row_base + r; if (grow >= n) grow = n - 1;
        cp_async16(xs_base + (unsigned)(r * X_STRIDE + c4 * 4) * 4,
                   x + (size_t)grow * D_IN + c4 * 4);
    }
    asm volatile("cp.async.commit_group;");

    #pragma unroll
    for (int l = 0; l < 16; l++) {
        int flat = tid + l * 256;
        int k  = flat >> 4;
        int cc = (flat & 15) * 4;
        float4 w = __ldg((const float4*)(W1 + (size_t)k * 64 + cc));
        Wsh[k * W_STRIDE + cc + 0] = f2tf32(w.x);
        Wsh[k * W_STRIDE + cc + 1] = f2tf32(w.y);
        Wsh[k * W_STRIDE + cc + 2] = f2tf32(w.z);
        Wsh[k * W_STRIDE + cc + 3] = f2tf32(w.w);
    }

    // fused zeroing of S1 / S2 (scatter targets)
    {
        int gtid = blockIdx.x * 256 + tid;
        int nthr = gridDim.x * 256;
        float4 z = make_float4(0.f, 0.f, 0.f, 0.f);
        for (int i = gtid; i < n * 16; i += nthr) ((float4*)g_S1)[i] = z;
        for (int i = gtid; i < n * 8;  i += nthr) ((float4*)g_S2)[i] = z;
    }

    float c[8][4];
    #pragma unroll
    for (int nt = 0; nt < 8; nt++)
        #pragma unroll
        for (int i = 0; i < 4; i++) c[nt][i] = 0.f;

    #pragma unroll
    for (int kc = 0; kc < 8; kc++) {
        if (kc + 1 < 8) {
            int buf = (kc + 1) & 1;
            #pragma unroll
            for (int l = 0; l < 4; l++) {
                int flat = tid + l * 256;
                int r    = flat >> 3;
                int c4   = flat & 7;
                int grow = row_base + r; if (grow >= n) grow = n - 1;
                cp_async16(xs_base + (unsigned)(buf * X_WORDS + r * X_STRIDE + c4 * 4) * 4,
                           x + (size_t)grow * D_IN + (kc + 1) * 32 + c4 * 4);
            }
            asm volatile("cp.async.commit_group;");
            asm volatile("cp.async.wait_group 1;");
        } else {
            asm volatile("cp.async.wait_group 0;");
        }
        __syncthreads();

        const unsigned* xb = (const unsigned*)(xsf + (kc & 1) * X_WORDS);
        #pragma unroll
        for (int k8 = 0; k8 < 4; k8++) {
            int ar = wm + qrow;
            int ac = k8 * 8 + qcol;
            unsigned a0 = bits2tf32(xb[(ar    ) * X_STRIDE + ac    ]);
            unsigned a1 = bits2tf32(xb[(ar + 8) * X_STRIDE + ac    ]);
            unsigned a2 = bits2tf32(xb[(ar    ) * X_STRIDE + ac + 4]);
            unsigned a3 = bits2tf32(xb[(ar + 8) * X_STRIDE + ac + 4]);
            int kg = kc * 32 + k8 * 8 + qcol;
            #pragma unroll
            for (int nt = 0; nt < 8; nt++) {
                unsigned b0 = Wsh[(kg    ) * W_STRIDE + nt * 8 + qrow];
                unsigned b1 = Wsh[(kg + 4) * W_STRIDE + nt * 8 + qrow];
                mma_tf32(c[nt][0], c[nt][1], c[nt][2], c[nt][3],
                         a0, a1, a2, a3, b0, b1);
            }
        }
        __syncthreads();
    }

    int r0 = row_base + wm + qrow;
    int cb = qcol * 2;
    #pragma unroll
    for (int nt = 0; nt < 8; nt++) {
        if (r0 < n)
            *(__half2*)(g_Hh + (size_t)r0 * D_HID + nt*8 + cb) =
                __floats2half2_rn(c[nt][0], c[nt][1]);
        if (r0 + 8 < n)
            *(__half2*)(g_Hh + (size_t)(r0 + 8) * D_HID + nt*8 + cb) =
                __floats2half2_rn(c[nt][2], c[nt][3]);
    }
}

// ---------------------------------------------------------------------------
// red helpers
// ---------------------------------------------------------------------------
__device__ __forceinline__ void red_add_v4(float* p, float4 v) {
    asm volatile("red.global.add.v4.f32 [%0], {%1,%2,%3,%4};"
                 :: "l"(p), "f"(v.x), "f"(v.y), "f"(v.z), "f"(v.w)
                 : "memory");
}
__device__ __forceinline__ void red_add_v2(float* p, float2 v) {
    asm volatile("red.global.add.v2.f32 [%0], {%1,%2};"
                 :: "l"(p), "f"(v.x), "f"(v.y)
                 : "memory");
}

// ---------------------------------------------------------------------------
// SpMM d=64: warp owns 32 edges; coalesced streaming index loads + shfl.
// ---------------------------------------------------------------------------
__global__ __launch_bounds__(256) void spmm64_kernel(
    const int* __restrict__ src, const int* __restrict__ dst,
    const float* __restrict__ val, int nnz)
{
    int lane = threadIdx.x & 31;
    long long wid = (long long)((blockIdx.x * blockDim.x + threadIdx.x) >> 5);
    long long wbase = wid * 32;
    if (wbase >= nnz) return;

    long long e = wbase + lane;
    bool ok = (e < nnz);
    long long ec = ok ? e : (nnz - 1);
    int   s = __ldcs(src + ec);
    int   d = __ldcs(dst + ec);
    float v = ok ? __ldcs(val + ec) : 0.f;

    int g = lane >> 4;          // group 0/1
    int c = lane & 15;          // channel quad

    #pragma unroll
    for (int j = 0; j < 16; j++) {
        int sl = g * 16 + j;
        int   sj = __shfl_sync(0xFFFFFFFFu, s, sl);
        int   dj = __shfl_sync(0xFFFFFFFFu, d, sl);
        float vj = __shfl_sync(0xFFFFFFFFu, v, sl);
        uint2 raw = __ldg((const uint2*)(g_Hh + (size_t)sj * D_HID) + c);
        float2 f0 = __half22float2(*(__half2*)&raw.x);
        float2 f1 = __half22float2(*(__half2*)&raw.y);
        red_add_v4(g_S1 + (size_t)dj * D_HID + c * 4,
                   make_float4(vj*f0.x, vj*f0.y, vj*f1.x, vj*f1.y));
    }
}

// ---------------------------------------------------------------------------
// GEMM2 (TF32 MMA): Z1 = relu(S1 + b1) @ W2   [n,64] @ [64,32], fp16 out.
// ---------------------------------------------------------------------------
#define Z_STRIDE 68
#define V_STRIDE 40

__global__ __launch_bounds__(256) void gemm2_mma_kernel(
    const float* __restrict__ b1, const float* __restrict__ W2, int n)
{
    __shared__ float    zs[128 * Z_STRIDE];
    __shared__ unsigned ws[64 * V_STRIDE];
    __shared__ float    b1s[64];

    int tid  = threadIdx.x;
    int warp = tid >> 5;
    int lane = tid & 31;
    int row_base = blockIdx.x * 128;
    int wm   = warp * 16;
    int qrow = lane >> 2;
    int qcol = lane & 3;

    unsigned zs_base;
    asm("{ .reg .u64 t; cvta.to.shared.u64 t, %1; cvt.u32.u64 %0, t; }"
        : "=r"(zs_base) : "l"(zs));

    #pragma unroll
    for (int l = 0; l < 8; l++) {
        int flat = tid + l * 256;
        int r  = flat >> 4;
        int c4 = flat & 15;
        int grow = row_base + r; if (grow >= n) grow = n - 1;
        cp_async16(zs_base + (unsigned)(r * Z_STRIDE + c4 * 4) * 4,
                   g_S1 + (size_t)grow * D_HID + c4 * 4);
    }
    asm volatile("cp.async.commit_group;");

    #pragma unroll
    for (int l = 0; l < 2; l++) {
        int flat = tid + l * 256;
        int k  = flat >> 3;
        int cc = (flat & 7) * 4;
        float4 w = __ldg((const float4*)(W2 + (size_t)k * 32 + cc));
        ws[k * V_STRIDE + cc + 0] = f2tf32(w.x);
        ws[k * V_STRIDE + cc + 1] = f2tf32(w.y);
        ws[k * V_STRIDE + cc + 2] = f2tf32(w.z);
        ws[k * V_STRIDE + cc + 3] = f2tf32(w.w);
    }
    if (tid < 64) b1s[tid] = __ldg(b1 + tid);

    asm volatile("cp.async.wait_group 0;");
    __syncthreads();

    float c[4][4];
    #pragma unroll
    for (int nt = 0; nt < 4; nt++)
        #pragma unroll
        for (int i = 0; i < 4; i++) c[nt][i] = 0.f;

    int ar = wm + qrow;
    #pragma unroll
    for (int k8 = 0; k8 < 8; k8++) {
        int k0 = k8 * 8 + qcol;
        float bz0 = b1s[k0];
        float bz1 = b1s[k0 + 4];
        unsigned a0 = f2tf32(fmaxf(zs[(ar    ) * Z_STRIDE + k0    ] + bz0, 0.f));
        unsigned a1 = f2tf32(fmaxf(zs[(ar + 8) * Z_STRIDE + k0    ] + bz0, 0.f));
        unsigned a2 = f2tf32(fmaxf(zs[(ar    ) * Z_STRIDE + k0 + 4] + bz1, 0.f));
        unsigned a3 = f2tf32(fmaxf(zs[(ar + 8) * Z_STRIDE + k0 + 4] + bz1, 0.f));
        #pragma unroll
        for (int nt = 0; nt < 4; nt++) {
            unsigned b0 = ws[(k0    ) * V_STRIDE + nt * 8 + qrow];
            unsigned b1v= ws[(k0 + 4) * V_STRIDE + nt * 8 + qrow];
            mma_tf32(c[nt][0], c[nt][1], c[nt][2], c[nt][3],
                     a0, a1, a2, a3, b0, b1v);
        }
    }

    int r0 = row_base + wm + qrow;
    int cb = qcol * 2;
    #pragma unroll
    for (int nt = 0; nt < 4; nt++) {
        if (r0 < n)
            *(__half2*)(g_Z1h + (size_t)r0 * D_EMB + nt*8 + cb) =
                __floats2half2_rn(c[nt][0], c[nt][1]);
        if (r0 + 8 < n)
            *(__half2*)(g_Z1h + (size_t)(r0 + 8) * D_EMB + nt*8 + cb) =
                __floats2half2_rn(c[nt][2], c[nt][3]);
    }
}

// ---------------------------------------------------------------------------
// SpMM d=32: warp owns 32 edges; 16 lanes per edge (float2 channel pair),
// red.v2 -> 2x red-issue parallelism vs 8-lane/red.v4 (matches spmm64 shape).
// ---------------------------------------------------------------------------
__global__ __launch_bounds__(256) void spmm32_kernel(
    const int* __restrict__ src, const int* __restrict__ dst,
    const float* __restrict__ val, int nnz)
{
    int lane = threadIdx.x & 31;
    long long wid = (long long)((blockIdx.x * blockDim.x + threadIdx.x) >> 5);
    long long wbase = wid * 32;
    if (wbase >= nnz) return;

    long long e = wbase + lane;
    bool ok = (e < nnz);
    long long ec = ok ? e : (nnz - 1);
    int   s = __ldcs(src + ec);
    int   d = __ldcs(dst + ec);
    float v = ok ? __ldcs(val + ec) : 0.f;

    int g = lane >> 4;          // group 0/1
    int c = lane & 15;          // channel pair index (2 floats)

    #pragma unroll
    for (int j = 0; j < 16; j++) {
        int sl = g * 16 + j;
        int   sj = __shfl_sync(0xFFFFFFFFu, s, sl);
        int   dj = __shfl_sync(0xFFFFFFFFu, d, sl);
        float vj = __shfl_sync(0xFFFFFFFFu, v, sl);
        unsigned raw = __ldg((const unsigned*)(g_Z1h + (size_t)sj * D_EMB) + c);
        float2 f = __half22float2(*(__half2*)&raw);
        red_add_v2(g_S2 + (size_t)dj * D_EMB + c * 2,
                   make_float2(vj * f.x, vj * f.y));
    }
}

// ---------------------------------------------------------------------------
// S2 fp32 -> fp16 with fused +b2.
// ---------------------------------------------------------------------------
__global__ __launch_bounds__(256) void s2half_kernel(
    const float* __restrict__ b2, int n4)
{
    int i = blockIdx.x * blockDim.x + threadIdx.x;
    if (i >= n4) return;
    float4 bb = __ldg((const float4*)b2 + (i & 7));
    float4 v = ((const float4*)g_S2)[i];
    ((__half2*)g_S2h)[i*2    ] = __floats2half2_rn(v.x + bb.x, v.y + bb.y);
    ((__half2*)g_S2h)[i*2 + 1] = __floats2half2_rn(v.z + bb.z, v.w + bb.w);
}

// ---------------------------------------------------------------------------
// Decoder: warp owns 32 edges; coalesced index loads + shfl distribution.
// ---------------------------------------------------------------------------
__global__ __launch_bounds__(256) void decoder_kernel(
    const int* __restrict__ edge_index, float* __restrict__ out, int ne)
{
    int lane = threadIdx.x & 31;
    long long wid = (long long)((blockIdx.x * blockDim.x + threadIdx.x) >> 5);
    long long wbase = wid * 32;
    if (wbase >= ne) return;

    long long e = wbase + lane;
    bool ok = (e < ne);
    long long ec = ok ? e : (ne - 1);
    int s = __ldcs(edge_index + ec);
    int d = __ldcs(edge_index + ne + ec);

    int g = lane >> 3;
    int c = lane & 7;

    float p[8];
    #pragma unroll
    for (int j = 0; j < 8; j++) {
        int sl = g * 8 + j;
        int sj = __shfl_sync(0xFFFFFFFFu, s, sl);
        int dj = __shfl_sync(0xFFFFFFFFu, d, sl);
        uint2 ra = __ldg((const uint2*)(g_S2h + (size_t)sj * D_EMB) + c);
        uint2 rb = __ldg((const uint2*)(g_S2h + (size_t)dj * D_EMB) + c);
        float2 al = __half22float2(*(__half2*)&ra.x);
        float2 ah = __half22float2(*(__half2*)&ra.y);
        float2 bl = __half22float2(*(__half2*)&rb.x);
        float2 bh = __half22float2(*(__half2*)&rb.y);
        p[j] = al.x*bl.x + al.y*bl.y + ah.x*bh.x + ah.y*bh.y;
    }

    #pragma unroll
    for (int m = 1; m < 8; m <<= 1) {
        #pragma unroll
        for (int j = 0; j < 8; j++)
            p[j] += __shfl_xor_sync(0xFFFFFFFFu, p[j], m);
    }

    long long eo = wbase + g * 8 + c;
    if (eo < ne) out[eo] = p[c];
}

// ---------------------------------------------------------------------------
extern "C" void kernel_launch(void* const* d_in, const int* in_sizes, int n_in,
                              void* d_out, int out_size)
{
    const float* x         = (const float*)d_in[0];
    const int*   adj_src   = (const int*)  d_in[1];
    const int*   adj_dst   = (const int*)  d_in[2];
    const float* adj_val   = (const float*)d_in[3];
    const int*   edge_idx  = (const int*)  d_in[4];
    const float* W1        = (const float*)d_in[5];
    const float* b1        = (const float*)d_in[6];
    const float* W2        = (const float*)d_in[7];
    const float* b2        = (const float*)d_in[8];
    float*       out       = (float*)d_out;

    int n   = in_sizes[0] / D_IN;
    int nnz = in_sizes[3];
    int ne  = in_sizes[4] / 2;
    (void)n_in; (void)out_size;

    // GEMM1 (TF32 + cp.async, fused S1/S2 zeroing, fp16 H)
    cudaFuncSetAttribute(gemm1_tf32_v4,
                         cudaFuncAttributeMaxDynamicSharedMemorySize, GEMM1_SMEM);
    gemm1_tf32_v4<<<(n + 127) / 128, 256, GEMM1_SMEM>>>(x, W1, n);

    // SpMM1 (d=64): 1 warp per 32 edges
    {
        long long warps = ((long long)nnz + 31) / 32;
        long long total = warps * 32;
        int blocks = (int)((total + 255) / 256);
        spmm64_kernel<<<blocks, 256>>>(adj_src, adj_dst, adj_val, nnz);
    }
    // GEMM2 (TF32 MMA, fused relu + b1, fp16 Z1)
    gemm2_mma_kernel<<<(n + 127) / 128, 256>>>(b1, W2, n);
    // SpMM2 (d=32): 1 warp per 32 edges, 16 lanes/edge, red.v2
    {
        long long warps = ((long long)nnz + 31) / 32;
        long long total = warps * 32;
        int blocks = (int)((total + 255) / 256);
        spmm32_kernel<<<blocks, 256>>>(adj_src, adj_dst, adj_val, nnz);
    }
    // S2 -> fp16 with +b2 folded
    {
        int n4 = n * 8;
        s2half_kernel<<<(n4 + 255) / 256, 256>>>(b2, n4);
    }
    // Decoder: 1 warp per 32 edges
    {
        long long warps = ((long long)ne + 31) / 32;
        long long total = warps * 32;
        int blocks = (int)((total + 255) / 256);
        decoder_kernel<<<blocks, 256>>>(edge_idx, out, ne);
    }
}